// round 4
// baseline (speedup 1.0000x reference)
#include <cuda_runtime.h>
#include <cuda_bf16.h>
#include <cstdint>

// Problem constants
#define H 64
#define B 16
#define L 512
#define OUT 2
#define TOKS_PER_BLOCK 16
#define BLOCKS_PER_BATCH (2 * L / TOKS_PER_BLOCK)    // 64
#define GRID1 (B * BLOCKS_PER_BATCH)                 // 1024

// Accumulator scratch + completion counter.
// Zero at module load; the finishing block resets both after use, so every
// graph replay sees them zeroed.
__device__ float g_h[B * H];
__device__ unsigned int g_count;

// ---------------------------------------------------------------------------
// Fused kernel: token gather + sos contraction + per-batch accumulation,
// with the tiny MLP classifier run inline by the LAST block to finish
// (completion-counter pattern) — saves a ~6us single-block launch.
//
// Gather thread layout (256 threads):
//   h4 = tid & 15   -> output columns h = 4*h4 .. 4*h4+3 (one float4)
//   wg = tid >> 4   -> rows w = wg, wg+16, wg+32, wg+48
// A warp's 32 LDG.128 cover two full 256-byte matrix rows -> fully coalesced.
// ---------------------------------------------------------------------------
__global__ __launch_bounds__(256, 8)
void fused_kernel(const int* __restrict__ s1,
                  const int* __restrict__ s2,
                  const float4* __restrict__ embed,
                  const float* __restrict__ sos,
                  const float* __restrict__ w1,
                  const float* __restrict__ b1,
                  const float* __restrict__ w2,
                  const float* __restrict__ b2,
                  float* __restrict__ out)
{
    const int bl  = blockIdx.x;
    const int b   = bl / BLOCKS_PER_BATCH;
    const int j0  = (bl % BLOCKS_PER_BATCH) * TOKS_PER_BLOCK;  // within [0, 1024)
    const int tid = threadIdx.x;
    const int h4  = tid & 15;
    const int wg  = tid >> 4;

    // This block's 16 tokens are entirely in s1 or entirely in s2.
    const int* sp = (j0 < L) ? (s1 + b * L + j0) : (s2 + b * L + (j0 - L));

    int toks[TOKS_PER_BLOCK];
    #pragma unroll
    for (int k = 0; k < TOKS_PER_BLOCK; k++)
        toks[k] = __ldg(&sp[k]);

    const float sw0 = __ldg(&sos[wg]);
    const float sw1 = __ldg(&sos[wg + 16]);
    const float sw2 = __ldg(&sos[wg + 32]);
    const float sw3 = __ldg(&sos[wg + 48]);

    float4 acc = make_float4(0.f, 0.f, 0.f, 0.f);

    #pragma unroll 4
    for (int k = 0; k < TOKS_PER_BLOCK; k++) {
        const float4* M = embed + (size_t)toks[k] * (H * H / 4);

        float4 m0 = __ldg(&M[(wg      ) * 16 + h4]);
        float4 m1 = __ldg(&M[(wg + 16) * 16 + h4]);
        float4 m2 = __ldg(&M[(wg + 32) * 16 + h4]);
        float4 m3 = __ldg(&M[(wg + 48) * 16 + h4]);

        acc.x = fmaf(sw0, m0.x, acc.x); acc.y = fmaf(sw0, m0.y, acc.y);
        acc.z = fmaf(sw0, m0.z, acc.z); acc.w = fmaf(sw0, m0.w, acc.w);
        acc.x = fmaf(sw1, m1.x, acc.x); acc.y = fmaf(sw1, m1.y, acc.y);
        acc.z = fmaf(sw1, m1.z, acc.z); acc.w = fmaf(sw1, m1.w, acc.w);
        acc.x = fmaf(sw2, m2.x, acc.x); acc.y = fmaf(sw2, m2.y, acc.y);
        acc.z = fmaf(sw2, m2.z, acc.z); acc.w = fmaf(sw2, m2.w, acc.w);
        acc.x = fmaf(sw3, m3.x, acc.x); acc.y = fmaf(sw3, m3.y, acc.y);
        acc.z = fmaf(sw3, m3.z, acc.z); acc.w = fmaf(sw3, m3.w, acc.w);
    }

    // Warp reduce: lane l and l+16 hold the same columns for adjacent wg rows.
    acc.x += __shfl_down_sync(0xffffffffu, acc.x, 16);
    acc.y += __shfl_down_sync(0xffffffffu, acc.y, 16);
    acc.z += __shfl_down_sync(0xffffffffu, acc.z, 16);
    acc.w += __shfl_down_sync(0xffffffffu, acc.w, 16);

    __shared__ float sh[8][H];
    const int warp = tid >> 5;
    const int lane = tid & 31;
    if (lane < 16) {
        sh[warp][lane * 4 + 0] = acc.x;
        sh[warp][lane * 4 + 1] = acc.y;
        sh[warp][lane * 4 + 2] = acc.z;
        sh[warp][lane * 4 + 3] = acc.w;
    }
    __syncthreads();
    if (tid < H) {
        float s = 0.f;
        #pragma unroll
        for (int w = 0; w < 8; w++) s += sh[w][tid];
        atomicAdd(&g_h[b * H + tid], s);
    }

    // ---- completion detection -------------------------------------------
    __threadfence();                       // make our g_h atomics visible
    __syncthreads();
    __shared__ unsigned int is_last;
    if (tid == 0)
        is_last = (atomicAdd(&g_count, 1u) == GRID1 - 1u) ? 1u : 0u;
    __syncthreads();
    if (!is_last) return;

    // ---- MLP epilogue (last block only, 256 threads) --------------------
    // out = relu(h @ w1^T + b1) @ w2^T + b2
    __shared__ float w1s[H][H + 1];        // padded -> conflict-free LDS
    __shared__ float hs[B * H];
    __shared__ float x[B][H];

    #pragma unroll
    for (int idx = tid; idx < H * H; idx += 256)
        w1s[idx >> 6][idx & 63] = __ldg(&w1[idx]);
    #pragma unroll
    for (int idx = tid; idx < B * H; idx += 256) {
        hs[idx] = __ldcg(&g_h[idx]);       // L2 read (producers wrote via L2 atomics)
        g_h[idx] = 0.0f;                   // reset for next graph replay
    }
    __syncthreads();

    // tid -> (batch bb = tid>>4, 4 hidden units j = (tid&15)*4 ..+3)
    {
        const int bb = tid >> 4;
        const int jb = (tid & 15) * 4;
        float a0 = __ldg(&b1[jb + 0]);
        float a1 = __ldg(&b1[jb + 1]);
        float a2 = __ldg(&b1[jb + 2]);
        float a3 = __ldg(&b1[jb + 3]);
        #pragma unroll
        for (int k = 0; k < H; k++) {
            const float hv = hs[bb * H + k];
            a0 = fmaf(hv, w1s[jb + 0][k], a0);
            a1 = fmaf(hv, w1s[jb + 1][k], a1);
            a2 = fmaf(hv, w1s[jb + 2][k], a2);
            a3 = fmaf(hv, w1s[jb + 3][k], a3);
        }
        x[bb][jb + 0] = fmaxf(a0, 0.f);
        x[bb][jb + 1] = fmaxf(a1, 0.f);
        x[bb][jb + 2] = fmaxf(a2, 0.f);
        x[bb][jb + 3] = fmaxf(a3, 0.f);
    }
    __syncthreads();

    if (tid < B * OUT) {
        const int bb = tid >> 1;
        const int o  = tid & 1;
        float a = __ldg(&b2[o]);
        #pragma unroll
        for (int k = 0; k < H; k++)
            a = fmaf(x[bb][k], __ldg(&w2[o * H + k]), a);
        out[bb * OUT + o] = a;
    }

    if (tid == 0) g_count = 0u;            // reset counter for next replay
}

// ---------------------------------------------------------------------------
// Launch
// Inputs (metadata order): s1, s2, embed, sos, w1, b1, w2, b2
// ---------------------------------------------------------------------------
extern "C" void kernel_launch(void* const* d_in, const int* in_sizes, int n_in,
                              void* d_out, int out_size)
{
    const int*    s1    = (const int*)   d_in[0];
    const int*    s2    = (const int*)   d_in[1];
    const float4* embed = (const float4*)d_in[2];
    const float*  sos   = (const float*) d_in[3];
    const float*  w1    = (const float*) d_in[4];
    const float*  b1    = (const float*) d_in[5];
    const float*  w2    = (const float*) d_in[6];
    const float*  b2    = (const float*) d_in[7];
    float* out = (float*)d_out;

    fused_kernel<<<GRID1, 256>>>(s1, s2, embed, sos, w1, b1, w2, b2, out);
}